// round 1
// baseline (speedup 1.0000x reference)
#include <cuda_runtime.h>
#include <math.h>

#define MTOT 4096      // B*S
#define NDIM 1024
#define SEQ  2048
#define HEADS 16
#define DH   64

// Scratch (allocation-free rule: __device__ globals)
__device__ float g_q[MTOT * NDIM];
__device__ float g_k[MTOT * NDIM];
__device__ float g_v[MTOT * NDIM];
__device__ float g_y[MTOT * NDIM];

// ---------------------------------------------------------------------------
// C[M,N] = A[M,K] @ B[N,K]^T (+ bias[N] if bias != nullptr)
// Classic 128x128x8 SIMT SGEMM, 256 threads, 8x8 micro-tile per thread.
// ---------------------------------------------------------------------------
__global__ __launch_bounds__(256) void sgemm_nt(
    const float* __restrict__ A, const float* __restrict__ B,
    float* __restrict__ C, const float* __restrict__ bias,
    int M, int N, int K)
{
    __shared__ float As[8][128];
    __shared__ float Bs[8][128];

    const int t  = threadIdx.x;
    const int tx = t & 15;        // 0..15 -> n micro
    const int ty = t >> 4;        // 0..15 -> m micro
    const int bm = blockIdx.y * 128;
    const int bn = blockIdx.x * 128;

    const int lrow = t >> 1;        // 0..127
    const int lcol = (t & 1) * 4;   // 0 or 4

    float acc[8][8];
#pragma unroll
    for (int i = 0; i < 8; i++)
#pragma unroll
        for (int j = 0; j < 8; j++) acc[i][j] = 0.f;

    for (int k0 = 0; k0 < K; k0 += 8) {
        float4 av = *(const float4*)(A + (size_t)(bm + lrow) * K + k0 + lcol);
        float4 bv = *(const float4*)(B + (size_t)(bn + lrow) * K + k0 + lcol);
        __syncthreads();
        As[lcol + 0][lrow] = av.x;
        As[lcol + 1][lrow] = av.y;
        As[lcol + 2][lrow] = av.z;
        As[lcol + 3][lrow] = av.w;
        Bs[lcol + 0][lrow] = bv.x;
        Bs[lcol + 1][lrow] = bv.y;
        Bs[lcol + 2][lrow] = bv.z;
        Bs[lcol + 3][lrow] = bv.w;
        __syncthreads();

#pragma unroll
        for (int kk = 0; kk < 8; kk++) {
            float a[8], b[8];
            *(float4*)(a)     = *(const float4*)&As[kk][ty * 8];
            *(float4*)(a + 4) = *(const float4*)&As[kk][ty * 8 + 4];
            *(float4*)(b)     = *(const float4*)&Bs[kk][tx * 8];
            *(float4*)(b + 4) = *(const float4*)&Bs[kk][tx * 8 + 4];
#pragma unroll
            for (int i = 0; i < 8; i++)
#pragma unroll
                for (int j = 0; j < 8; j++)
                    acc[i][j] = fmaf(a[i], b[j], acc[i][j]);
        }
    }

#pragma unroll
    for (int i = 0; i < 8; i++) {
        const int row = bm + ty * 8 + i;
#pragma unroll
        for (int j4 = 0; j4 < 8; j4 += 4) {
            const int col = bn + tx * 8 + j4;
            float4 o;
            o.x = acc[i][j4 + 0];
            o.y = acc[i][j4 + 1];
            o.z = acc[i][j4 + 2];
            o.w = acc[i][j4 + 3];
            if (bias) {
                o.x += bias[col + 0];
                o.y += bias[col + 1];
                o.z += bias[col + 2];
                o.w += bias[col + 3];
            }
            *(float4*)(C + (size_t)row * N + col) = o;
        }
    }
}

// ---------------------------------------------------------------------------
// Flash attention: per block = one (b, h, 64-row q tile).
// Q/K/V are [B,S,D] fp32; head slice at column h*64, row stride NDIM.
// 256 threads: thread (ty,tx) owns q rows ty*4+i, (kv or dh) cols tx*4+j.
// smem: Qs[d][q] str65, Ks[d][kv] str65, Ps[q][kv] str65, Vs[kv][dh] str64.
// ---------------------------------------------------------------------------
#define QS_OFF 0
#define KS_OFF (64 * 65)
#define PS_OFF (2 * 64 * 65)
#define VS_OFF (3 * 64 * 65)
#define ATTN_SMEM_BYTES ((3 * 64 * 65 + 64 * 64) * 4)

__global__ __launch_bounds__(256) void attn_kernel(
    const float* __restrict__ Q, const float* __restrict__ K,
    const float* __restrict__ V, float* __restrict__ Y)
{
    extern __shared__ float sm[];
    float* Qs = sm + QS_OFF;
    float* Ks = sm + KS_OFF;
    float* Ps = sm + PS_OFF;
    float* Vs = sm + VS_OFF;

    const int t  = threadIdx.x;
    const int tx = t & 15;
    const int ty = t >> 4;
    const int q0 = blockIdx.x * 64;
    const int h  = blockIdx.y;
    const int b  = blockIdx.z;

    const size_t base = (size_t)b * SEQ * NDIM + h * DH;
    const float* Qb = Q + base;
    const float* Kb = K + base;
    const float* Vb = V + base;

    // load Q tile, transposed into smem: Qs[d][q]
    {
        const int c = (t & 15) * 4;
#pragma unroll
        for (int it = 0; it < 4; it++) {
            const int r = (t >> 4) + it * 16;
            float4 v4 = *(const float4*)(Qb + (size_t)(q0 + r) * NDIM + c);
            Qs[(c + 0) * 65 + r] = v4.x;
            Qs[(c + 1) * 65 + r] = v4.y;
            Qs[(c + 2) * 65 + r] = v4.z;
            Qs[(c + 3) * 65 + r] = v4.w;
        }
    }

    float m[4], l[4], o[4][4];
#pragma unroll
    for (int i = 0; i < 4; i++) {
        m[i] = -1e30f;
        l[i] = 0.f;
#pragma unroll
        for (int j = 0; j < 4; j++) o[i][j] = 0.f;
    }

    const float scale = 0.125f;  // 1/sqrt(64)

    for (int kt = 0; kt < SEQ / 64; kt++) {
        const int kv0 = kt * 64;
        __syncthreads();  // previous PV done before overwriting Ks/Vs
        {
            const int c = (t & 15) * 4;
#pragma unroll
            for (int it = 0; it < 4; it++) {
                const int r = (t >> 4) + it * 16;
                float4 k4 = *(const float4*)(Kb + (size_t)(kv0 + r) * NDIM + c);
                Ks[(c + 0) * 65 + r] = k4.x;
                Ks[(c + 1) * 65 + r] = k4.y;
                Ks[(c + 2) * 65 + r] = k4.z;
                Ks[(c + 3) * 65 + r] = k4.w;
                float4 v4 = *(const float4*)(Vb + (size_t)(kv0 + r) * NDIM + c);
                *(float4*)&Vs[r * 64 + c] = v4;
            }
        }
        __syncthreads();

        // S = Q K^T  (per-thread 4x4 of the 64x64 tile)
        float s[4][4];
#pragma unroll
        for (int i = 0; i < 4; i++)
#pragma unroll
            for (int j = 0; j < 4; j++) s[i][j] = 0.f;

#pragma unroll 8
        for (int d = 0; d < 64; d++) {
            float qf[4], kf[4];
#pragma unroll
            for (int i = 0; i < 4; i++) qf[i] = Qs[d * 65 + ty * 4 + i];
#pragma unroll
            for (int j = 0; j < 4; j++) kf[j] = Ks[d * 65 + tx * 4 + j];
#pragma unroll
            for (int i = 0; i < 4; i++)
#pragma unroll
                for (int j = 0; j < 4; j++)
                    s[i][j] = fmaf(qf[i], kf[j], s[i][j]);
        }

        // online softmax update per q row
#pragma unroll
        for (int i = 0; i < 4; i++) {
            float tm = -1e30f;
#pragma unroll
            for (int j = 0; j < 4; j++) {
                s[i][j] *= scale;
                tm = fmaxf(tm, s[i][j]);
            }
#pragma unroll
            for (int off = 8; off > 0; off >>= 1)
                tm = fmaxf(tm, __shfl_xor_sync(0xffffffffu, tm, off, 16));
            const float mn = fmaxf(m[i], tm);
            const float corr = __expf(m[i] - mn);
            float rs = 0.f;
#pragma unroll
            for (int j = 0; j < 4; j++) {
                const float p = __expf(s[i][j] - mn);
                s[i][j] = p;
                rs += p;
            }
#pragma unroll
            for (int off = 8; off > 0; off >>= 1)
                rs += __shfl_xor_sync(0xffffffffu, rs, off, 16);
            l[i] = l[i] * corr + rs;
            m[i] = mn;
#pragma unroll
            for (int j = 0; j < 4; j++) o[i][j] *= corr;
#pragma unroll
            for (int j = 0; j < 4; j++)
                Ps[(ty * 4 + i) * 65 + tx * 4 + j] = s[i][j];
        }
        __syncthreads();

        // O += P @ V
#pragma unroll 8
        for (int j = 0; j < 64; j++) {
            float pf[4];
#pragma unroll
            for (int i = 0; i < 4; i++) pf[i] = Ps[(ty * 4 + i) * 65 + j];
            float4 vf = *(const float4*)&Vs[j * 64 + tx * 4];
#pragma unroll
            for (int i = 0; i < 4; i++) {
                o[i][0] = fmaf(pf[i], vf.x, o[i][0]);
                o[i][1] = fmaf(pf[i], vf.y, o[i][1]);
                o[i][2] = fmaf(pf[i], vf.z, o[i][2]);
                o[i][3] = fmaf(pf[i], vf.w, o[i][3]);
            }
        }
    }

    // normalize + store to Y [B,S,D]
#pragma unroll
    for (int i = 0; i < 4; i++) {
        const float inv = 1.f / l[i];
        const size_t row = (size_t)b * SEQ + q0 + ty * 4 + i;
        float4 out;
        out.x = o[i][0] * inv;
        out.y = o[i][1] * inv;
        out.z = o[i][2] * inv;
        out.w = o[i][3] * inv;
        *(float4*)(Y + row * NDIM + h * DH + tx * 4) = out;
    }
}

extern "C" void kernel_launch(void* const* d_in, const int* in_sizes, int n_in,
                              void* d_out, int out_size)
{
    const float* x  = (const float*)d_in[0];
    const float* wq = (const float*)d_in[1];
    const float* wk = (const float*)d_in[2];
    const float* wv = (const float*)d_in[3];
    const float* wo = (const float*)d_in[4];
    const float* bo = (const float*)d_in[5];
    float* out = (float*)d_out;

    float *q, *k, *v, *y;
    cudaGetSymbolAddress((void**)&q, g_q);
    cudaGetSymbolAddress((void**)&k, g_k);
    cudaGetSymbolAddress((void**)&v, g_v);
    cudaGetSymbolAddress((void**)&y, g_y);

    cudaFuncSetAttribute(attn_kernel,
                         cudaFuncAttributeMaxDynamicSharedMemorySize,
                         ATTN_SMEM_BYTES);

    dim3 gemm_grid(NDIM / 128, MTOT / 128);
    sgemm_nt<<<gemm_grid, 256>>>(x, wq, q, nullptr, MTOT, NDIM, NDIM);
    sgemm_nt<<<gemm_grid, 256>>>(x, wk, k, nullptr, MTOT, NDIM, NDIM);
    sgemm_nt<<<gemm_grid, 256>>>(x, wv, v, nullptr, MTOT, NDIM, NDIM);

    dim3 attn_grid(SEQ / 64, HEADS, 2);
    attn_kernel<<<attn_grid, 256, ATTN_SMEM_BYTES>>>(q, k, v, y);

    sgemm_nt<<<gemm_grid, 256>>>(y, wo, out, bo, MTOT, NDIM, NDIM);
}

// round 3
// speedup vs baseline: 1.4898x; 1.4898x over previous
#include <cuda_runtime.h>
#include <cuda_bf16.h>
#include <cstdint>
#include <math.h>

#define MTOT 4096      // B*S
#define NDIM 1024
#define SEQ  2048
#define HEADS 16
#define DH   64

#define KP     3072            // tripled K for bf16x3
#define KC     64              // bf16 K elements per smem stage (128 B rows)
#define NC     (KP / KC)       // 48
#define NS     3
#define STAGE_BYTES 32768      // A tile 16KB + B tile 16KB
#define GEMM_SMEM (NS * STAGE_BYTES)   // 96 KB

// ---------------------------------------------------------------------------
// Scratch (allocation-free rule: __device__ globals)
// ---------------------------------------------------------------------------
__device__ float g_q[MTOT * NDIM];
__device__ float g_k[MTOT * NDIM];
__device__ float g_v[MTOT * NDIM];
__device__ float g_y[MTOT * NDIM];
__device__ __nv_bfloat16 g_x3[MTOT * KP];
__device__ __nv_bfloat16 g_y3[MTOT * KP];
__device__ __nv_bfloat16 g_w3[4][NDIM * KP];

// ---------------------------------------------------------------------------
// PTX helpers (sm_80-baseline features only: cp.async / ldmatrix / mma.sync)
// ---------------------------------------------------------------------------
__device__ __forceinline__ uint32_t smem_u32(const void* p) {
    uint32_t a;
    asm("{ .reg .u64 t; cvta.to.shared.u64 t, %1; cvt.u32.u64 %0, t; }"
        : "=r"(a) : "l"(p));
    return a;
}

__device__ __forceinline__ void cp_async16(uint32_t dst, const void* src) {
    asm volatile("cp.async.cg.shared.global [%0], [%1], 16;"
                 :: "r"(dst), "l"(src));
}
#define CP_COMMIT() asm volatile("cp.async.commit_group;" ::: "memory")
#define CP_WAIT(n)  asm volatile("cp.async.wait_group %0;" :: "n"(n) : "memory")

__device__ __forceinline__ void ldsm_x4(uint32_t& r0, uint32_t& r1,
                                        uint32_t& r2, uint32_t& r3,
                                        uint32_t addr) {
    asm volatile("ldmatrix.sync.aligned.m8n8.x4.shared.b16 {%0,%1,%2,%3}, [%4];"
                 : "=r"(r0), "=r"(r1), "=r"(r2), "=r"(r3) : "r"(addr));
}

__device__ __forceinline__ void mma_bf16(float* d, const uint32_t* a,
                                         const uint32_t* b) {
    asm volatile(
        "mma.sync.aligned.m16n8k16.row.col.f32.bf16.bf16.f32 "
        "{%0,%1,%2,%3}, {%4,%5,%6,%7}, {%8,%9}, {%0,%1,%2,%3};"
        : "+f"(d[0]), "+f"(d[1]), "+f"(d[2]), "+f"(d[3])
        : "r"(a[0]), "r"(a[1]), "r"(a[2]), "r"(a[3]), "r"(b[0]), "r"(b[1]));
}

// ---------------------------------------------------------------------------
// fp32 -> bf16x3 conversion kernels. X[rows,1024] -> Y[rows,3072].
//   A-side layout: [hi | lo | hi];  B-side layout: [hi | hi | lo]
// ---------------------------------------------------------------------------
template <int ASIDE>
__global__ __launch_bounds__(256) void cvt3(const float* __restrict__ X,
                                            __nv_bfloat16* __restrict__ Y,
                                            int total4) {
    int i = blockIdx.x * 256 + threadIdx.x;
    if (i >= total4) return;
    int r = i >> 8;
    int c = (i & 255) * 4;
    float4 v = *(const float4*)(X + (size_t)r * NDIM + c);
    float f[4] = {v.x, v.y, v.z, v.w};
    __nv_bfloat16 hi[4], lo[4];
#pragma unroll
    for (int j = 0; j < 4; j++) {
        hi[j] = __float2bfloat16(f[j]);
        lo[j] = __float2bfloat16(f[j] - __bfloat162float(hi[j]));
    }
    __nv_bfloat16* base = Y + (size_t)r * KP;
    __nv_bfloat162 h01 = __halves2bfloat162(hi[0], hi[1]);
    __nv_bfloat162 h23 = __halves2bfloat162(hi[2], hi[3]);
    __nv_bfloat162 l01 = __halves2bfloat162(lo[0], lo[1]);
    __nv_bfloat162 l23 = __halves2bfloat162(lo[2], lo[3]);
    *(__nv_bfloat162*)(base + c)     = h01;
    *(__nv_bfloat162*)(base + c + 2) = h23;
    if (ASIDE) {  // [hi | lo | hi]
        *(__nv_bfloat162*)(base + NDIM + c)         = l01;
        *(__nv_bfloat162*)(base + NDIM + c + 2)     = l23;
        *(__nv_bfloat162*)(base + 2 * NDIM + c)     = h01;
        *(__nv_bfloat162*)(base + 2 * NDIM + c + 2) = h23;
    } else {      // [hi | hi | lo]
        *(__nv_bfloat162*)(base + NDIM + c)         = h01;
        *(__nv_bfloat162*)(base + NDIM + c + 2)     = h23;
        *(__nv_bfloat162*)(base + 2 * NDIM + c)     = l01;
        *(__nv_bfloat162*)(base + 2 * NDIM + c + 2) = l23;
    }
}

// ---------------------------------------------------------------------------
// HMMA bf16 GEMM: C[M,N] = A[M,KP] @ B[N,KP]^T (+bias), K-major bf16.
// CTA tile 128x128, 8 warps (2x4), 3-stage cp.async pipeline,
// SW128 xor swizzle, ldmatrix + mma.sync.m16n8k16.
// ---------------------------------------------------------------------------
__global__ __launch_bounds__(256) void gemm_bf3(
    const __nv_bfloat16* __restrict__ A, const __nv_bfloat16* __restrict__ B,
    float* __restrict__ C, const float* __restrict__ bias, int M, int N)
{
    extern __shared__ char smraw[];
    const uint32_t smA = smem_u32(smraw);

    const int t   = threadIdx.x;
    const int wid = t >> 5;
    const int lid = t & 31;
    const int wm  = wid >> 2;    // 0..1: 64-row group
    const int wn  = wid & 3;     // 0..3: 32-col group
    const int bm  = blockIdx.y * 128;
    const int bn  = blockIdx.x * 128;

    float acc[4][4][4];
#pragma unroll
    for (int mi = 0; mi < 4; mi++)
#pragma unroll
        for (int ni = 0; ni < 4; ni++)
#pragma unroll
            for (int j = 0; j < 4; j++) acc[mi][ni][j] = 0.f;

    // load mapping: thread t loads 16B chunk (row lr+32i, chunk lc) for A and B
    const int lr = t >> 3;     // 0..31
    const int lc = t & 7;      // chunk 0..7 (8 bf16 each)
    const __nv_bfloat16* Ab = A + (size_t)(bm + lr) * KP + lc * 8;
    const __nv_bfloat16* Bb = B + (size_t)(bn + lr) * KP + lc * 8;

#define LOAD_STAGE(kc, s)                                                     \
    do {                                                                      \
        uint32_t sa_ = smA + (s) * STAGE_BYTES;                               \
        uint32_t sb_ = sa_ + 16384;                                           \
        const __nv_bfloat16* ag_ = Ab + (kc) * KC;                            \
        const __nv_bfloat16* bg_ = Bb + (kc) * KC;                            \
        _Pragma("unroll")                                                     \
        for (int i_ = 0; i_ < 4; i_++) {                                      \
            int r_ = lr + 32 * i_;                                            \
            uint32_t off_ = r_ * 128 + ((lc ^ (r_ & 7)) << 4);                \
            cp_async16(sa_ + off_, ag_ + (size_t)32 * i_ * KP);               \
            cp_async16(sb_ + off_, bg_ + (size_t)32 * i_ * KP);               \
        }                                                                     \
    } while (0)

    LOAD_STAGE(0, 0); CP_COMMIT();
    LOAD_STAGE(1, 1); CP_COMMIT();

    for (int kc = 0; kc < NC; kc++) {
        if (kc + NS - 1 < NC) LOAD_STAGE(kc + NS - 1, (kc + NS - 1) % NS);
        CP_COMMIT();
        CP_WAIT(2);
        __syncthreads();

        const uint32_t sa = smA + (kc % NS) * STAGE_BYTES;
        const uint32_t sb = sa + 16384;

#pragma unroll
        for (int ks = 0; ks < 4; ks++) {
            uint32_t afr[4][4];
            uint32_t bfr[4][2];
#pragma unroll
            for (int mi = 0; mi < 4; mi++) {
                const int r = wm * 64 + mi * 16 + (lid & 15);
                const int c = 2 * ks + (lid >> 4);
                ldsm_x4(afr[mi][0], afr[mi][1], afr[mi][2], afr[mi][3],
                        sa + r * 128 + ((c ^ (r & 7)) << 4));
            }
#pragma unroll
            for (int np = 0; np < 2; np++) {
                const int r = wn * 32 + np * 16 + (lid >> 4) * 8 + (lid & 7);
                const int c = 2 * ks + ((lid >> 3) & 1);
                uint32_t b0, b1, b2, b3;
                ldsm_x4(b0, b1, b2, b3, sb + r * 128 + ((c ^ (r & 7)) << 4));
                bfr[np * 2][0] = b0;
                bfr[np * 2][1] = b1;
                bfr[np * 2 + 1][0] = b2;
                bfr[np * 2 + 1][1] = b3;
            }
#pragma unroll
            for (int mi = 0; mi < 4; mi++)
#pragma unroll
                for (int ni = 0; ni < 4; ni++)
                    mma_bf16(acc[mi][ni], afr[mi], bfr[ni]);
        }
        __syncthreads();
    }

    // epilogue: direct float2 stores
    const int r0 = lid >> 2;
    const int c0 = (lid & 3) * 2;
#pragma unroll
    for (int mi = 0; mi < 4; mi++) {
#pragma unroll
        for (int ni = 0; ni < 4; ni++) {
            const int row = bm + wm * 64 + mi * 16 + r0;
            const int col = bn + wn * 32 + ni * 8 + c0;
            float2 v0 = {acc[mi][ni][0], acc[mi][ni][1]};
            float2 v1 = {acc[mi][ni][2], acc[mi][ni][3]};
            if (bias) {
                const float bx = bias[col], by = bias[col + 1];
                v0.x += bx; v0.y += by;
                v1.x += bx; v1.y += by;
            }
            *(float2*)(C + (size_t)row * N + col) = v0;
            *(float2*)(C + (size_t)(row + 8) * N + col) = v1;
        }
    }
}

// ---------------------------------------------------------------------------
// Flash attention (fp32 SIMT, unchanged)
// ---------------------------------------------------------------------------
#define QS_OFF 0
#define KS_OFF (64 * 65)
#define PS_OFF (2 * 64 * 65)
#define VS_OFF (3 * 64 * 65)
#define ATTN_SMEM_BYTES ((3 * 64 * 65 + 64 * 64) * 4)

__global__ __launch_bounds__(256) void attn_kernel(
    const float* __restrict__ Q, const float* __restrict__ K,
    const float* __restrict__ V, float* __restrict__ Y)
{
    extern __shared__ float sm[];
    float* Qs = sm + QS_OFF;
    float* Ks = sm + KS_OFF;
    float* Ps = sm + PS_OFF;
    float* Vs = sm + VS_OFF;

    const int t  = threadIdx.x;
    const int tx = t & 15;
    const int ty = t >> 4;
    const int q0 = blockIdx.x * 64;
    const int h  = blockIdx.y;
    const int b  = blockIdx.z;

    const size_t base = (size_t)b * SEQ * NDIM + h * DH;
    const float* Qb = Q + base;
    const float* Kb = K + base;
    const float* Vb = V + base;

    {
        const int c = (t & 15) * 4;
#pragma unroll
        for (int it = 0; it < 4; it++) {
            const int r = (t >> 4) + it * 16;
            float4 v4 = *(const float4*)(Qb + (size_t)(q0 + r) * NDIM + c);
            Qs[(c + 0) * 65 + r] = v4.x;
            Qs[(c + 1) * 65 + r] = v4.y;
            Qs[(c + 2) * 65 + r] = v4.z;
            Qs[(c + 3) * 65 + r] = v4.w;
        }
    }

    float m[4], l[4], o[4][4];
#pragma unroll
    for (int i = 0; i < 4; i++) {
        m[i] = -1e30f;
        l[i] = 0.f;
#pragma unroll
        for (int j = 0; j < 4; j++) o[i][j] = 0.f;
    }

    const float scale = 0.125f;

    for (int kt = 0; kt < SEQ / 64; kt++) {
        const int kv0 = kt * 64;
        __syncthreads();
        {
            const int c = (t & 15) * 4;
#pragma unroll
            for (int it = 0; it < 4; it++) {
                const int r = (t >> 4) + it * 16;
                float4 k4 = *(const float4*)(Kb + (size_t)(kv0 + r) * NDIM + c);
                Ks[(c + 0) * 65 + r] = k4.x;
                Ks[(c + 1) * 65 + r] = k4.y;
                Ks[(c + 2) * 65 + r] = k4.z;
                Ks[(c + 3) * 65 + r] = k4.w;
                float4 v4 = *(const float4*)(Vb + (size_t)(kv0 + r) * NDIM + c);
                *(float4*)&Vs[r * 64 + c] = v4;
            }
        }
        __syncthreads();

        float s[4][4];
#pragma unroll
        for (int i = 0; i < 4; i++)
#pragma unroll
            for (int j = 0; j < 4; j++) s[i][j] = 0.f;

#pragma unroll 8
        for (int d = 0; d < 64; d++) {
            float qf[4], kf[4];
#pragma unroll
            for (int i = 0; i < 4; i++) qf[i] = Qs[d * 65 + ty * 4 + i];
#pragma unroll
            for (int j = 0; j < 4; j++) kf[j] = Ks[d * 65 + tx * 4 + j];
#pragma unroll
            for (int i = 0; i < 4; i++)
#pragma unroll
                for (int j = 0; j < 4; j++)
                    s[i][j] = fmaf(qf[i], kf[j], s[i][j]);
        }

#pragma unroll
        for (int i = 0; i < 4; i++) {
            float tm = -1e30f;
#pragma unroll
            for (int j = 0; j < 4; j++) {
                s[i][j] *= scale;
                tm = fmaxf(tm, s[i][j]);
            }
#pragma unroll
            for (int off = 8; off > 0; off >>= 1)
                tm = fmaxf(tm, __shfl_xor_sync(0xffffffffu, tm, off, 16));
            const float mn = fmaxf(m[i], tm);
            const float corr = __expf(m[i] - mn);
            float rs = 0.f;
#pragma unroll
            for (int j = 0; j < 4; j++) {
                const float p = __expf(s[i][j] - mn);
                s[i][j] = p;
                rs += p;
            }
#pragma unroll
            for (int off = 8; off > 0; off >>= 1)
                rs += __shfl_xor_sync(0xffffffffu, rs, off, 16);
            l[i] = l[i] * corr + rs;
            m[i] = mn;
#pragma unroll
            for (int j = 0; j < 4; j++) o[i][j] *= corr;
#pragma unroll
            for (int j = 0; j < 4; j++)
                Ps[(ty * 4 + i) * 65 + tx * 4 + j] = s[i][j];
        }
        __syncthreads();

#pragma unroll 8
        for (int j = 0; j < 64; j++) {
            float pf[4];
#pragma unroll
            for (int i = 0; i < 4; i++) pf[i] = Ps[(ty * 4 + i) * 65 + j];
            float4 vf = *(const float4*)&Vs[j * 64 + tx * 4];
#pragma unroll
            for (int i = 0; i < 4; i++) {
                o[i][0] = fmaf(pf[i], vf.x, o[i][0]);
                o[i][1] = fmaf(pf[i], vf.y, o[i][1]);
                o[i][2] = fmaf(pf[i], vf.z, o[i][2]);
                o[i][3] = fmaf(pf[i], vf.w, o[i][3]);
            }
        }
    }

#pragma unroll
    for (int i = 0; i < 4; i++) {
        const float inv = 1.f / l[i];
        const size_t row = (size_t)b * SEQ + q0 + ty * 4 + i;
        float4 out;
        out.x = o[i][0] * inv;
        out.y = o[i][1] * inv;
        out.z = o[i][2] * inv;
        out.w = o[i][3] * inv;
        *(float4*)(Y + row * NDIM + h * DH + tx * 4) = out;
    }
}

// ---------------------------------------------------------------------------
extern "C" void kernel_launch(void* const* d_in, const int* in_sizes, int n_in,
                              void* d_out, int out_size)
{
    const float* x  = (const float*)d_in[0];
    const float* wq = (const float*)d_in[1];
    const float* wk = (const float*)d_in[2];
    const float* wv = (const float*)d_in[3];
    const float* wo = (const float*)d_in[4];
    const float* bo = (const float*)d_in[5];
    float* out = (float*)d_out;

    float *q, *k, *v, *y;
    __nv_bfloat16 *x3, *y3, *w3;
    cudaGetSymbolAddress((void**)&q, g_q);
    cudaGetSymbolAddress((void**)&k, g_k);
    cudaGetSymbolAddress((void**)&v, g_v);
    cudaGetSymbolAddress((void**)&y, g_y);
    cudaGetSymbolAddress((void**)&x3, g_x3);
    cudaGetSymbolAddress((void**)&y3, g_y3);
    cudaGetSymbolAddress((void**)&w3, g_w3);
    __nv_bfloat16* wq3 = w3 + 0 * (size_t)NDIM * KP;
    __nv_bfloat16* wk3 = w3 + 1 * (size_t)NDIM * KP;
    __nv_bfloat16* wv3 = w3 + 2 * (size_t)NDIM * KP;
    __nv_bfloat16* wo3 = w3 + 3 * (size_t)NDIM * KP;

    cudaFuncSetAttribute(attn_kernel,
                         cudaFuncAttributeMaxDynamicSharedMemorySize,
                         ATTN_SMEM_BYTES);
    cudaFuncSetAttribute(gemm_bf3,
                         cudaFuncAttributeMaxDynamicSharedMemorySize,
                         GEMM_SMEM);

    // conversions
    cvt3<1><<<MTOT, 256>>>(x, x3, MTOT * 256);
    cvt3<0><<<NDIM, 256>>>(wq, wq3, NDIM * 256);
    cvt3<0><<<NDIM, 256>>>(wk, wk3, NDIM * 256);
    cvt3<0><<<NDIM, 256>>>(wv, wv3, NDIM * 256);
    cvt3<0><<<NDIM, 256>>>(wo, wo3, NDIM * 256);

    dim3 ggrid(NDIM / 128, MTOT / 128);
    gemm_bf3<<<ggrid, 256, GEMM_SMEM>>>(x3, wq3, q, nullptr, MTOT, NDIM);
    gemm_bf3<<<ggrid, 256, GEMM_SMEM>>>(x3, wk3, k, nullptr, MTOT, NDIM);
    gemm_bf3<<<ggrid, 256, GEMM_SMEM>>>(x3, wv3, v, nullptr, MTOT, NDIM);

    dim3 attn_grid(SEQ / 64, HEADS, 2);
    attn_kernel<<<attn_grid, 256, ATTN_SMEM_BYTES>>>(q, k, v, y);

    cvt3<1><<<MTOT, 256>>>(y, y3, MTOT * 256);
    gemm_bf3<<<ggrid, 256, GEMM_SMEM>>>(y3, wo3, out, bo, MTOT, NDIM);
}

// round 5
// speedup vs baseline: 4.1690x; 2.7983x over previous
#include <cuda_runtime.h>
#include <cuda_bf16.h>
#include <cstdint>
#include <math.h>

#define MTOT 4096      // B*S
#define NDIM 1024
#define SEQ  2048
#define HEADS 16
#define DH   64

#define KP     3072            // tripled K for bf16x3
#define KC     64              // bf16 K elements per smem stage (128 B rows)
#define NC     (KP / KC)       // 48
#define NS     3
#define STAGE_BYTES 32768      // A tile 16KB + B tile 16KB
#define GEMM_SMEM (NS * STAGE_BYTES)   // 96 KB

// ---------------------------------------------------------------------------
// Scratch (allocation-free rule: __device__ globals)
// ---------------------------------------------------------------------------
__device__ __nv_bfloat16 g_qb[MTOT * NDIM];
__device__ __nv_bfloat16 g_kb[MTOT * NDIM];
__device__ __nv_bfloat16 g_vb[MTOT * NDIM];
__device__ float g_y[MTOT * NDIM];
__device__ __nv_bfloat16 g_x3[MTOT * KP];
__device__ __nv_bfloat16 g_y3[MTOT * KP];
__device__ __nv_bfloat16 g_w3[4][NDIM * KP];

// ---------------------------------------------------------------------------
// PTX helpers (sm_80-baseline features only: cp.async / ldmatrix / mma.sync)
// ---------------------------------------------------------------------------
__device__ __forceinline__ uint32_t smem_u32(const void* p) {
    uint32_t a;
    asm("{ .reg .u64 t; cvta.to.shared.u64 t, %1; cvt.u32.u64 %0, t; }"
        : "=r"(a) : "l"(p));
    return a;
}

__device__ __forceinline__ void cp_async16(uint32_t dst, const void* src) {
    asm volatile("cp.async.cg.shared.global [%0], [%1], 16;"
                 :: "r"(dst), "l"(src));
}
#define CP_COMMIT() asm volatile("cp.async.commit_group;" ::: "memory")
#define CP_WAIT(n)  asm volatile("cp.async.wait_group %0;" :: "n"(n) : "memory")

__device__ __forceinline__ void ldsm_x4(uint32_t& r0, uint32_t& r1,
                                        uint32_t& r2, uint32_t& r3,
                                        uint32_t addr) {
    asm volatile("ldmatrix.sync.aligned.m8n8.x4.shared.b16 {%0,%1,%2,%3}, [%4];"
                 : "=r"(r0), "=r"(r1), "=r"(r2), "=r"(r3) : "r"(addr));
}

__device__ __forceinline__ void ldsm_x4_t(uint32_t& r0, uint32_t& r1,
                                          uint32_t& r2, uint32_t& r3,
                                          uint32_t addr) {
    asm volatile("ldmatrix.sync.aligned.m8n8.x4.trans.shared.b16 {%0,%1,%2,%3}, [%4];"
                 : "=r"(r0), "=r"(r1), "=r"(r2), "=r"(r3) : "r"(addr));
}

__device__ __forceinline__ void mma_bf16(float* d, const uint32_t* a,
                                         const uint32_t* b) {
    asm volatile(
        "mma.sync.aligned.m16n8k16.row.col.f32.bf16.bf16.f32 "
        "{%0,%1,%2,%3}, {%4,%5,%6,%7}, {%8,%9}, {%0,%1,%2,%3};"
        : "+f"(d[0]), "+f"(d[1]), "+f"(d[2]), "+f"(d[3])
        : "r"(a[0]), "r"(a[1]), "r"(a[2]), "r"(a[3]), "r"(b[0]), "r"(b[1]));
}

__device__ __forceinline__ uint32_t pack_bf16(float a, float b) {
    __nv_bfloat162 h = __float22bfloat162_rn(make_float2(a, b));
    return *reinterpret_cast<uint32_t*>(&h);
}

// ---------------------------------------------------------------------------
// fp32 -> bf16x3 conversion. X[rows,1024] -> Y[rows,3072].
//   A-side layout: [hi | lo | hi];  B-side layout: [hi | hi | lo]
// ---------------------------------------------------------------------------
template <int ASIDE>
__global__ __launch_bounds__(256) void cvt3(const float* __restrict__ X,
                                            __nv_bfloat16* __restrict__ Y,
                                            int total4) {
    int i = blockIdx.x * 256 + threadIdx.x;
    if (i >= total4) return;
    int r = i >> 8;
    int c = (i & 255) * 4;
    float4 v = *(const float4*)(X + (size_t)r * NDIM + c);
    float f[4] = {v.x, v.y, v.z, v.w};
    __nv_bfloat16 hi[4], lo[4];
#pragma unroll
    for (int j = 0; j < 4; j++) {
        hi[j] = __float2bfloat16(f[j]);
        lo[j] = __float2bfloat16(f[j] - __bfloat162float(hi[j]));
    }
    __nv_bfloat16* base = Y + (size_t)r * KP;
    __nv_bfloat162 h01 = __halves2bfloat162(hi[0], hi[1]);
    __nv_bfloat162 h23 = __halves2bfloat162(hi[2], hi[3]);
    __nv_bfloat162 l01 = __halves2bfloat162(lo[0], lo[1]);
    __nv_bfloat162 l23 = __halves2bfloat162(lo[2], lo[3]);
    *(__nv_bfloat162*)(base + c)     = h01;
    *(__nv_bfloat162*)(base + c + 2) = h23;
    if (ASIDE) {
        *(__nv_bfloat162*)(base + NDIM + c)         = l01;
        *(__nv_bfloat162*)(base + NDIM + c + 2)     = l23;
        *(__nv_bfloat162*)(base + 2 * NDIM + c)     = h01;
        *(__nv_bfloat162*)(base + 2 * NDIM + c + 2) = h23;
    } else {
        *(__nv_bfloat162*)(base + NDIM + c)         = h01;
        *(__nv_bfloat162*)(base + NDIM + c + 2)     = h23;
        *(__nv_bfloat162*)(base + 2 * NDIM + c)     = l01;
        *(__nv_bfloat162*)(base + 2 * NDIM + c + 2) = l23;
    }
}

// ---------------------------------------------------------------------------
// HMMA bf16 GEMM: C[M,N] = scale * A[M,KP] @ B[N,KP]^T (+bias), K-major bf16.
// Output fp32 (BF16OUT=0, with bias) or bf16 (BF16OUT=1).
// ---------------------------------------------------------------------------
template <int BF16OUT>
__global__ __launch_bounds__(256) void gemm_bf3(
    const __nv_bfloat16* __restrict__ A, const __nv_bfloat16* __restrict__ B,
    void* __restrict__ Cv, const float* __restrict__ bias, float scale,
    int M, int N)
{
    extern __shared__ char smraw[];
    const uint32_t smA = smem_u32(smraw);

    const int t   = threadIdx.x;
    const int wid = t >> 5;
    const int lid = t & 31;
    const int wm  = wid >> 2;
    const int wn  = wid & 3;
    const int bm  = blockIdx.y * 128;
    const int bn  = blockIdx.x * 128;

    float acc[4][4][4];
#pragma unroll
    for (int mi = 0; mi < 4; mi++)
#pragma unroll
        for (int ni = 0; ni < 4; ni++)
#pragma unroll
            for (int j = 0; j < 4; j++) acc[mi][ni][j] = 0.f;

    const int lr = t >> 3;
    const int lc = t & 7;
    const __nv_bfloat16* Ab = A + (size_t)(bm + lr) * KP + lc * 8;
    const __nv_bfloat16* Bb = B + (size_t)(bn + lr) * KP + lc * 8;

#define LOAD_STAGE(kc, s)                                                     \
    do {                                                                      \
        uint32_t sa_ = smA + (s) * STAGE_BYTES;                               \
        uint32_t sb_ = sa_ + 16384;                                           \
        const __nv_bfloat16* ag_ = Ab + (kc) * KC;                            \
        const __nv_bfloat16* bg_ = Bb + (kc) * KC;                            \
        _Pragma("unroll")                                                     \
        for (int i_ = 0; i_ < 4; i_++) {                                      \
            int r_ = lr + 32 * i_;                                            \
            uint32_t off_ = r_ * 128 + ((lc ^ (r_ & 7)) << 4);                \
            cp_async16(sa_ + off_, ag_ + (size_t)32 * i_ * KP);               \
            cp_async16(sb_ + off_, bg_ + (size_t)32 * i_ * KP);               \
        }                                                                     \
    } while (0)

    LOAD_STAGE(0, 0); CP_COMMIT();
    LOAD_STAGE(1, 1); CP_COMMIT();

    for (int kc = 0; kc < NC; kc++) {
        if (kc + NS - 1 < NC) LOAD_STAGE(kc + NS - 1, (kc + NS - 1) % NS);
        CP_COMMIT();
        CP_WAIT(2);
        __syncthreads();

        const uint32_t sa = smA + (kc % NS) * STAGE_BYTES;
        const uint32_t sb = sa + 16384;

#pragma unroll
        for (int ks = 0; ks < 4; ks++) {
            uint32_t afr[4][4];
            uint32_t bfr[4][2];
#pragma unroll
            for (int mi = 0; mi < 4; mi++) {
                const int r = wm * 64 + mi * 16 + (lid & 15);
                const int c = 2 * ks + (lid >> 4);
                ldsm_x4(afr[mi][0], afr[mi][1], afr[mi][2], afr[mi][3],
                        sa + r * 128 + ((c ^ (r & 7)) << 4));
            }
#pragma unroll
            for (int np = 0; np < 2; np++) {
                const int r = wn * 32 + np * 16 + (lid >> 4) * 8 + (lid & 7);
                const int c = 2 * ks + ((lid >> 3) & 1);
                uint32_t b0, b1, b2, b3;
                ldsm_x4(b0, b1, b2, b3, sb + r * 128 + ((c ^ (r & 7)) << 4));
                bfr[np * 2][0] = b0;
                bfr[np * 2][1] = b1;
                bfr[np * 2 + 1][0] = b2;
                bfr[np * 2 + 1][1] = b3;
            }
#pragma unroll
            for (int mi = 0; mi < 4; mi++)
#pragma unroll
                for (int ni = 0; ni < 4; ni++)
                    mma_bf16(acc[mi][ni], afr[mi], bfr[ni]);
        }
        __syncthreads();
    }

    const int r0 = lid >> 2;
    const int c0 = (lid & 3) * 2;
#pragma unroll
    for (int mi = 0; mi < 4; mi++) {
#pragma unroll
        for (int ni = 0; ni < 4; ni++) {
            const int row = bm + wm * 64 + mi * 16 + r0;
            const int col = bn + wn * 32 + ni * 8 + c0;
            float2 v0 = {acc[mi][ni][0] * scale, acc[mi][ni][1] * scale};
            float2 v1 = {acc[mi][ni][2] * scale, acc[mi][ni][3] * scale};
            if (BF16OUT) {
                __nv_bfloat16* C = (__nv_bfloat16*)Cv;
                *(__nv_bfloat162*)(C + (size_t)row * N + col) =
                    __float22bfloat162_rn(v0);
                *(__nv_bfloat162*)(C + (size_t)(row + 8) * N + col) =
                    __float22bfloat162_rn(v1);
            } else {
                float* C = (float*)Cv;
                if (bias) {
                    const float bx = bias[col], by = bias[col + 1];
                    v0.x += bx; v0.y += by;
                    v1.x += bx; v1.y += by;
                }
                *(float2*)(C + (size_t)row * N + col) = v0;
                *(float2*)(C + (size_t)(row + 8) * N + col) = v1;
            }
        }
    }
}

// ---------------------------------------------------------------------------
// Tensor-core flash attention (bf16 in / fp32 softmax + accum / fp32 out).
// CTA = (128 q rows, one head, one batch). 8 warps x 16 q rows.
// K/V 64-row tiles, cp.async double-buffered, SW128 swizzle.
// Scale 1/8 is pre-folded into Q (projection epilogue).
// ---------------------------------------------------------------------------
__global__ __launch_bounds__(256, 1) void attn_tc(
    const __nv_bfloat16* __restrict__ Q, const __nv_bfloat16* __restrict__ K,
    const __nv_bfloat16* __restrict__ V, float* __restrict__ Y)
{
    __shared__ char sm_[32768];
    const uint32_t smb = smem_u32(sm_);

    const int t    = threadIdx.x;
    const int lane = t & 31;
    const int w    = t >> 5;
    const int q0   = blockIdx.x * 128;
    const int h    = blockIdx.y;
    const int b    = blockIdx.z;

    const size_t base = (size_t)b * SEQ * NDIM + h * DH;
    const __nv_bfloat16* Qb = Q + base;
    const __nv_bfloat16* Kb = K + base;
    const __nv_bfloat16* Vb = V + base;

    // ---- load Q tile (128 x 64 bf16) into smem, swizzled ----
#pragma unroll
    for (int i = 0; i < 4; i++) {
        const int u = t + 256 * i;          // 0..1023
        const int r = u >> 3;
        const int ch = u & 7;
        cp_async16(smb + r * 128 + ((ch ^ (r & 7)) << 4),
                   Qb + (size_t)(q0 + r) * NDIM + ch * 8);
    }
    CP_COMMIT();
    CP_WAIT(0);
    __syncthreads();

    // ---- Q fragments (persistent) ----
    uint32_t qf[4][4];
#pragma unroll
    for (int ks = 0; ks < 4; ks++) {
        const int r = w * 16 + (lane & 15);
        const int c = 2 * ks + (lane >> 4);
        ldsm_x4(qf[ks][0], qf[ks][1], qf[ks][2], qf[ks][3],
                smb + r * 128 + ((c ^ (r & 7)) << 4));
    }
    __syncthreads();

    // KV stages: [K0 8K][V0 8K][K1 8K][V1 8K]
#define LOAD_KV(kt, s)                                                        \
    do {                                                                      \
        const int kv0_ = (kt) * 64;                                           \
        const uint32_t stk_ = smb + (s) * 16384;                              \
        const uint32_t stv_ = stk_ + 8192;                                    \
        const int r_ = t >> 3, ch_ = t & 7;                                   \
        _Pragma("unroll")                                                     \
        for (int hf_ = 0; hf_ < 2; hf_++) {                                   \
            const int rr_ = r_ + 32 * hf_;                                    \
            const uint32_t off_ = rr_ * 128 + ((ch_ ^ (rr_ & 7)) << 4);       \
            cp_async16(stk_ + off_,                                           \
                       Kb + (size_t)(kv0_ + rr_) * NDIM + ch_ * 8);           \
            cp_async16(stv_ + off_,                                           \
                       Vb + (size_t)(kv0_ + rr_) * NDIM + ch_ * 8);           \
        }                                                                     \
    } while (0)

    LOAD_KV(0, 0);
    CP_COMMIT();

    float m0 = -1e30f, m1 = -1e30f, l0 = 0.f, l1 = 0.f;
    float oacc[8][4];
#pragma unroll
    for (int nb = 0; nb < 8; nb++)
#pragma unroll
        for (int j = 0; j < 4; j++) oacc[nb][j] = 0.f;

    for (int kt = 0; kt < SEQ / 64; kt++) {
        CP_WAIT(0);
        __syncthreads();
        if (kt + 1 < SEQ / 64) {
            LOAD_KV(kt + 1, (kt + 1) & 1);
            CP_COMMIT();
        }
        const uint32_t stk = smb + (kt & 1) * 16384;
        const uint32_t stv = stk + 8192;

        // ---- S = Q K^T ----
        float sacc[8][4];
#pragma unroll
        for (int nb = 0; nb < 8; nb++)
#pragma unroll
            for (int j = 0; j < 4; j++) sacc[nb][j] = 0.f;

#pragma unroll
        for (int ks = 0; ks < 4; ks++) {
#pragma unroll
            for (int np = 0; np < 4; np++) {
                const int r = np * 16 + (lane >> 4) * 8 + (lane & 7);
                const int c = 2 * ks + ((lane >> 3) & 1);
                uint32_t b0, b1, b2, b3;
                ldsm_x4(b0, b1, b2, b3, stk + r * 128 + ((c ^ (r & 7)) << 4));
                uint32_t bf0[2] = {b0, b1}, bf1[2] = {b2, b3};
                mma_bf16(sacc[np * 2], qf[ks], bf0);
                mma_bf16(sacc[np * 2 + 1], qf[ks], bf1);
            }
        }

        // ---- online softmax ----
        float mx0 = -1e30f, mx1 = -1e30f;
#pragma unroll
        for (int nb = 0; nb < 8; nb++) {
            mx0 = fmaxf(mx0, fmaxf(sacc[nb][0], sacc[nb][1]));
            mx1 = fmaxf(mx1, fmaxf(sacc[nb][2], sacc[nb][3]));
        }
        mx0 = fmaxf(mx0, __shfl_xor_sync(0xffffffffu, mx0, 1));
        mx0 = fmaxf(mx0, __shfl_xor_sync(0xffffffffu, mx0, 2));
        mx1 = fmaxf(mx1, __shfl_xor_sync(0xffffffffu, mx1, 1));
        mx1 = fmaxf(mx1, __shfl_xor_sync(0xffffffffu, mx1, 2));

        const float mn0 = fmaxf(m0, mx0);
        const float mn1 = fmaxf(m1, mx1);
        const float corr0 = __expf(m0 - mn0);
        const float corr1 = __expf(m1 - mn1);
        m0 = mn0; m1 = mn1;

        float sum0 = 0.f, sum1 = 0.f;
#pragma unroll
        for (int nb = 0; nb < 8; nb++) {
            float p0 = __expf(sacc[nb][0] - mn0);
            float p1 = __expf(sacc[nb][1] - mn0);
            float p2 = __expf(sacc[nb][2] - mn1);
            float p3 = __expf(sacc[nb][3] - mn1);
            sacc[nb][0] = p0; sacc[nb][1] = p1;
            sacc[nb][2] = p2; sacc[nb][3] = p3;
            sum0 += p0 + p1;
            sum1 += p2 + p3;
        }
        sum0 += __shfl_xor_sync(0xffffffffu, sum0, 1);
        sum0 += __shfl_xor_sync(0xffffffffu, sum0, 2);
        sum1 += __shfl_xor_sync(0xffffffffu, sum1, 1);
        sum1 += __shfl_xor_sync(0xffffffffu, sum1, 2);
        l0 = l0 * corr0 + sum0;
        l1 = l1 * corr1 + sum1;

#pragma unroll
        for (int nb = 0; nb < 8; nb++) {
            oacc[nb][0] *= corr0;
            oacc[nb][1] *= corr0;
            oacc[nb][2] *= corr1;
            oacc[nb][3] *= corr1;
        }

        // ---- pack P to bf16 a-frags ----
        uint32_t pa[4][4];
#pragma unroll
        for (int ks = 0; ks < 4; ks++) {
            pa[ks][0] = pack_bf16(sacc[2 * ks][0], sacc[2 * ks][1]);
            pa[ks][1] = pack_bf16(sacc[2 * ks][2], sacc[2 * ks][3]);
            pa[ks][2] = pack_bf16(sacc[2 * ks + 1][0], sacc[2 * ks + 1][1]);
            pa[ks][3] = pack_bf16(sacc[2 * ks + 1][2], sacc[2 * ks + 1][3]);
        }

        // ---- O += P V ----
#pragma unroll
        for (int ks = 0; ks < 4; ks++) {
#pragma unroll
            for (int np = 0; np < 4; np++) {
                const int r = ks * 16 + (lane & 15);
                const int c = np * 2 + (lane >> 4);
                uint32_t b0, b1, b2, b3;
                ldsm_x4_t(b0, b1, b2, b3,
                          stv + r * 128 + ((c ^ (r & 7)) << 4));
                uint32_t bf0[2] = {b0, b1}, bf1[2] = {b2, b3};
                mma_bf16(oacc[np * 2], pa[ks], bf0);
                mma_bf16(oacc[np * 2 + 1], pa[ks], bf1);
            }
        }
    }

    // ---- normalize + store ----
    const float inv0 = 1.f / l0;
    const float inv1 = 1.f / l1;
    const size_t row0 = (size_t)b * SEQ + q0 + w * 16 + (lane >> 2);
    const size_t row1 = row0 + 8;
#pragma unroll
    for (int nb = 0; nb < 8; nb++) {
        const int col = h * DH + nb * 8 + (lane & 3) * 2;
        float2 v0 = {oacc[nb][0] * inv0, oacc[nb][1] * inv0};
        float2 v1 = {oacc[nb][2] * inv1, oacc[nb][3] * inv1};
        *(float2*)(Y + row0 * NDIM + col) = v0;
        *(float2*)(Y + row1 * NDIM + col) = v1;
    }
}

// ---------------------------------------------------------------------------
extern "C" void kernel_launch(void* const* d_in, const int* in_sizes, int n_in,
                              void* d_out, int out_size)
{
    const float* x  = (const float*)d_in[0];
    const float* wq = (const float*)d_in[1];
    const float* wk = (const float*)d_in[2];
    const float* wv = (const float*)d_in[3];
    const float* wo = (const float*)d_in[4];
    const float* bo = (const float*)d_in[5];
    float* out = (float*)d_out;

    __nv_bfloat16 *qb, *kb, *vb, *x3, *y3, *w3;
    float* y;
    cudaGetSymbolAddress((void**)&qb, g_qb);
    cudaGetSymbolAddress((void**)&kb, g_kb);
    cudaGetSymbolAddress((void**)&vb, g_vb);
    cudaGetSymbolAddress((void**)&y, g_y);
    cudaGetSymbolAddress((void**)&x3, g_x3);
    cudaGetSymbolAddress((void**)&y3, g_y3);
    cudaGetSymbolAddress((void**)&w3, g_w3);
    __nv_bfloat16* wq3 = w3 + 0 * (size_t)NDIM * KP;
    __nv_bfloat16* wk3 = w3 + 1 * (size_t)NDIM * KP;
    __nv_bfloat16* wv3 = w3 + 2 * (size_t)NDIM * KP;
    __nv_bfloat16* wo3 = w3 + 3 * (size_t)NDIM * KP;

    cudaFuncSetAttribute(gemm_bf3<0>,
                         cudaFuncAttributeMaxDynamicSharedMemorySize, GEMM_SMEM);
    cudaFuncSetAttribute(gemm_bf3<1>,
                         cudaFuncAttributeMaxDynamicSharedMemorySize, GEMM_SMEM);

    // conversions
    cvt3<1><<<MTOT, 256>>>(x, x3, MTOT * 256);
    cvt3<0><<<NDIM, 256>>>(wq, wq3, NDIM * 256);
    cvt3<0><<<NDIM, 256>>>(wk, wk3, NDIM * 256);
    cvt3<0><<<NDIM, 256>>>(wv, wv3, NDIM * 256);
    cvt3<0><<<NDIM, 256>>>(wo, wo3, NDIM * 256);

    dim3 ggrid(NDIM / 128, MTOT / 128);
    // Q gets the 1/sqrt(Dh)=0.125 scale folded in (exact in bf16)
    gemm_bf3<1><<<ggrid, 256, GEMM_SMEM>>>(x3, wq3, qb, nullptr, 0.125f, MTOT, NDIM);
    gemm_bf3<1><<<ggrid, 256, GEMM_SMEM>>>(x3, wk3, kb, nullptr, 1.0f, MTOT, NDIM);
    gemm_bf3<1><<<ggrid, 256, GEMM_SMEM>>>(x3, wv3, vb, nullptr, 1.0f, MTOT, NDIM);

    dim3 attn_grid(SEQ / 128, HEADS, 2);
    attn_tc<<<attn_grid, 256>>>(qb, kb, vb, y);

    cvt3<1><<<MTOT, 256>>>(y, y3, MTOT * 256);
    gemm_bf3<0><<<ggrid, 256, GEMM_SMEM>>>(y3, wo3, out, bo, 1.0f, MTOT, NDIM);
}